// round 7
// baseline (speedup 1.0000x reference)
#include <cuda_runtime.h>
#include <cuda_bf16.h>
#include <stdint.h>
#include <math.h>

// Problem dims
#define BB 2048
#define SS 32
#define DD 1024
#define PP 16
#define FF 512
#define HH 512

// ---------------- scratch layout (single __device__ array, float units) -----
#define N_T1     ((size_t)BB * SS * DD)
#define N_H      ((size_t)BB * SS * HH)
#define N_ATTN   ((size_t)BB * SS * SS)
#define N_DAV    ((size_t)BB * SS)
#define N_HEAD   ((size_t)3 * BB * FF)
#define N_FAVF   ((size_t)2 * BB * DD)
#define E_Q      ((size_t)BB * SS * DD)
#define E_W1     ((size_t)SS * HH * DD)
#define E_MT     ((size_t)DD * DD)
#define E_WT     ((size_t)2 * DD * DD)
#define E_WVW    ((size_t)DD * DD)
#define E_OUTW   ((size_t)DD * DD)
#define E_HW     ((size_t)3 * FF * DD)
#define E_AVMIX  ((size_t)2 * BB * DD)
#define E_AVPRE  ((size_t)2 * BB * DD)
#define E_FAV    ((size_t)3 * BB * DD)

#define OF_T1     ((size_t)0)
#define OF_H      (OF_T1 + N_T1)
#define OF_ATTN   (OF_H + N_H)
#define OF_DAV    (OF_ATTN + N_ATTN)
#define OF_HEAD   (OF_DAV + N_DAV)
#define OF_FAVF   (OF_HEAD + N_HEAD)
#define OF_QS     (OF_FAVF + N_FAVF)
#define OF_W1S    (OF_QS + E_Q)
#define OF_MTS    (OF_W1S + E_W1)
#define OF_WTS    (OF_MTS + E_MT)
#define OF_WVWS   (OF_WTS + E_WT)
#define OF_OUTWS  (OF_WVWS + E_WVW)
#define OF_HWS    (OF_OUTWS + E_OUTW)
#define OF_AVMIXS (OF_HWS + E_HW)
#define OF_AVPRES (OF_AVMIXS + E_AVMIX)
#define OF_FAVS   (OF_AVPRES + E_AVPRE)
#define OF_WV     (OF_FAVS + E_FAV)
#define SCRATCH_FLOATS (OF_WV + 1024)

__device__ float g_scratch[SCRATCH_FLOATS];

// ======================= helpers ===========================================
__device__ __forceinline__ uint32_t smem_u32(const void* p) {
    uint32_t a;
    asm("{ .reg .u64 t; cvta.to.shared.u64 t, %1; cvt.u32.u64 %0, t; }"
        : "=r"(a) : "l"(p));
    return a;
}
__device__ __forceinline__ uint32_t pk2(__nv_bfloat16 a, __nv_bfloat16 b) {
    __nv_bfloat162 t = __halves2bfloat162(a, b);
    return *reinterpret_cast<uint32_t*>(&t);
}

#define LDSM_X4(r0, r1, r2, r3, addr) \
    asm volatile("ldmatrix.sync.aligned.m8n8.x4.shared.b16 {%0,%1,%2,%3}, [%4];" \
                 : "=r"(r0), "=r"(r1), "=r"(r2), "=r"(r3) : "r"(addr))

#define MMA16816(d, a, b0, b1) \
    asm volatile("mma.sync.aligned.m16n8k16.row.col.f32.bf16.bf16.f32 " \
                 "{%0,%1,%2,%3}, {%4,%5,%6,%7}, {%8,%9}, {%0,%1,%2,%3};" \
                 : "+f"((d)[0]), "+f"((d)[1]), "+f"((d)[2]), "+f"((d)[3]) \
                 : "r"((a)[0]), "r"((a)[1]), "r"((a)[2]), "r"((a)[3]), \
                   "r"(b0), "r"(b1))

#define CP_ASYNC16(smaddr, gptr) \
    asm volatile("cp.async.cg.shared.global [%0], [%1], 16;" \
                 :: "r"(smaddr), "l"(gptr))
#define CP_COMMIT() asm volatile("cp.async.commit_group;")
#define CP_WAIT1()  asm volatile("cp.async.wait_group 1;")

// ===========================================================================
// Split-bf16 3-pass NT GEMM on HMMA, pre-split bf16 hi/lo inputs.
//   C[m,n] = sum_k A[m,k]*Bt[n,k] (+bias[n]) (+relu)
// CTA tile 128x256, BK=32, 256 threads (8 warps, warp tile 64x64, 2m x 4n).
// cp.async 3-stage pipeline; AST=80 row stride -> conflict-free LDSM.
// Output: fp32 (Cf) and/or bf16 hi/lo split (Chi/Clo).
// ===========================================================================
#define AST 80
#define OFF_ALO 10240
#define OFF_BHI 20480
#define OFF_BLO 40960
#define STAGE_BYTES 61440
#define N_STAGES 3

__global__ __launch_bounds__(256)
void mma_gemm(const __nv_bfloat16* __restrict__ Ahi, const __nv_bfloat16* __restrict__ Alo,
              long long lda, long long zA,
              const __nv_bfloat16* __restrict__ Bhi, const __nv_bfloat16* __restrict__ Blo,
              long long ldb, long long zB,
              const float* __restrict__ bias, long long zBias,
              float* __restrict__ Cf, __nv_bfloat16* __restrict__ Chi,
              __nv_bfloat16* __restrict__ Clo, long long ldc, long long zC,
              int K, int relu)
{
    extern __shared__ __align__(16) char smem[];
    const uint32_t sb = smem_u32(smem);

    const long long zz = blockIdx.z;
    Ahi += zz * zA; Alo += zz * zA;
    Bhi += zz * zB; Blo += zz * zB;
    if (Cf)  Cf  += zz * zC;
    if (Chi) { Chi += zz * zC; Clo += zz * zC; }
    if (bias) bias += zz * zBias;

    const int tid = threadIdx.x;
    const int wid = tid >> 5, lid = tid & 31;
    const long long bm = (long long)blockIdx.y * 128;
    const long long bn = (long long)blockIdx.x * 256;
    const int wm = (wid & 1) * 64;     // 2 m-groups
    const int wn = (wid >> 1) * 64;    // 4 n-groups

    float acc[4][8][4];
#pragma unroll
    for (int mt = 0; mt < 4; mt++)
#pragma unroll
        for (int nt = 0; nt < 8; nt++)
#pragma unroll
            for (int r = 0; r < 4; r++) acc[mt][nt][r] = 0.0f;

    const int qd = lid >> 3, qr = lid & 7;

    // cp.async geometry: A 512 chunks/plane (2 per thread), B 1024 (4 per thread)
    const int arow0 = tid >> 1;                 // chunks t: row=c>>2 -> c=t*? use c=t and t+256
    // chunk id c: row=c>>2, ch=c&3
#define A_ROW(c) ((c) >> 2)
#define A_CH(c)  ((c) & 3)
    const int ca0 = tid, ca1 = tid + 256;
    const int cb0 = tid, cb1 = tid + 256, cb2 = tid + 512, cb3 = tid + 768;

#define FETCH_ASYNC(st, k0) do {                                                       \
    uint32_t bp = sb + (st) * STAGE_BYTES;                                             \
    CP_ASYNC16(bp + A_ROW(ca0) * AST + A_CH(ca0) * 16,                                 \
               Ahi + (bm + A_ROW(ca0)) * lda + (k0) + A_CH(ca0) * 8);                  \
    CP_ASYNC16(bp + A_ROW(ca1) * AST + A_CH(ca1) * 16,                                 \
               Ahi + (bm + A_ROW(ca1)) * lda + (k0) + A_CH(ca1) * 8);                  \
    CP_ASYNC16(bp + OFF_ALO + A_ROW(ca0) * AST + A_CH(ca0) * 16,                       \
               Alo + (bm + A_ROW(ca0)) * lda + (k0) + A_CH(ca0) * 8);                  \
    CP_ASYNC16(bp + OFF_ALO + A_ROW(ca1) * AST + A_CH(ca1) * 16,                       \
               Alo + (bm + A_ROW(ca1)) * lda + (k0) + A_CH(ca1) * 8);                  \
    CP_ASYNC16(bp + OFF_BHI + A_ROW(cb0) * AST + A_CH(cb0) * 16,                       \
               Bhi + (bn + A_ROW(cb0)) * ldb + (k0) + A_CH(cb0) * 8);                  \
    CP_ASYNC16(bp + OFF_BHI + A_ROW(cb1) * AST + A_CH(cb1) * 16,                       \
               Bhi + (bn + A_ROW(cb1)) * ldb + (k0) + A_CH(cb1) * 8);                  \
    CP_ASYNC16(bp + OFF_BHI + A_ROW(cb2) * AST + A_CH(cb2) * 16,                       \
               Bhi + (bn + A_ROW(cb2)) * ldb + (k0) + A_CH(cb2) * 8);                  \
    CP_ASYNC16(bp + OFF_BHI + A_ROW(cb3) * AST + A_CH(cb3) * 16,                       \
               Bhi + (bn + A_ROW(cb3)) * ldb + (k0) + A_CH(cb3) * 8);                  \
    CP_ASYNC16(bp + OFF_BLO + A_ROW(cb0) * AST + A_CH(cb0) * 16,                       \
               Blo + (bn + A_ROW(cb0)) * ldb + (k0) + A_CH(cb0) * 8);                  \
    CP_ASYNC16(bp + OFF_BLO + A_ROW(cb1) * AST + A_CH(cb1) * 16,                       \
               Blo + (bn + A_ROW(cb1)) * ldb + (k0) + A_CH(cb1) * 8);                  \
    CP_ASYNC16(bp + OFF_BLO + A_ROW(cb2) * AST + A_CH(cb2) * 16,                       \
               Blo + (bn + A_ROW(cb2)) * ldb + (k0) + A_CH(cb2) * 8);                  \
    CP_ASYNC16(bp + OFF_BLO + A_ROW(cb3) * AST + A_CH(cb3) * 16,                       \
               Blo + (bn + A_ROW(cb3)) * ldb + (k0) + A_CH(cb3) * 8);                  \
} while (0)

    const int nIter = K >> 5;
    FETCH_ASYNC(0, 0);
    CP_COMMIT();
    FETCH_ASYNC(1, 32);
    CP_COMMIT();

    for (int it = 0; it < nIter; it++) {
        CP_WAIT1();
        __syncthreads();
        if (it + 2 < nIter) {
            int st2 = (it + 2) % N_STAGES;
            FETCH_ASYNC(st2, (it + 2) * 32);
        }
        CP_COMMIT();

        const uint32_t sbase = sb + (it % N_STAGES) * STAGE_BYTES;
#pragma unroll
        for (int kk = 0; kk < 32; kk += 16) {
            uint32_t ah[4][4], al[4][4], bh[4][4], bl[4][4];
#pragma unroll
            for (int mt = 0; mt < 4; mt++) {
                uint32_t row = wm + mt * 16 + (qd & 1) * 8 + qr;
                uint32_t off = row * AST + kk * 2 + (qd >> 1) * 16;
                LDSM_X4(ah[mt][0], ah[mt][1], ah[mt][2], ah[mt][3], sbase + off);
                LDSM_X4(al[mt][0], al[mt][1], al[mt][2], al[mt][3], sbase + OFF_ALO + off);
            }
#pragma unroll
            for (int ng = 0; ng < 4; ng++) {
                uint32_t row = wn + ng * 16 + (qd >> 1) * 8 + qr;
                uint32_t off = row * AST + kk * 2 + (qd & 1) * 16;
                LDSM_X4(bh[ng][0], bh[ng][1], bh[ng][2], bh[ng][3], sbase + OFF_BHI + off);
                LDSM_X4(bl[ng][0], bl[ng][1], bl[ng][2], bl[ng][3], sbase + OFF_BLO + off);
            }
#pragma unroll
            for (int mt = 0; mt < 4; mt++)
#pragma unroll
                for (int nt = 0; nt < 8; nt++) {
                    int n2 = nt >> 1, o = (nt & 1) * 2;
                    MMA16816(acc[mt][nt], ah[mt], bh[n2][o], bh[n2][o + 1]);
                }
#pragma unroll
            for (int mt = 0; mt < 4; mt++)
#pragma unroll
                for (int nt = 0; nt < 8; nt++) {
                    int n2 = nt >> 1, o = (nt & 1) * 2;
                    MMA16816(acc[mt][nt], ah[mt], bl[n2][o], bl[n2][o + 1]);
                }
#pragma unroll
            for (int mt = 0; mt < 4; mt++)
#pragma unroll
                for (int nt = 0; nt < 8; nt++) {
                    int n2 = nt >> 1, o = (nt & 1) * 2;
                    MMA16816(acc[mt][nt], al[mt], bh[n2][o], bh[n2][o + 1]);
                }
        }
        __syncthreads();
    }

    // ---- epilogue ----
    const int mrow = lid >> 2, ncol = (lid & 3) * 2;
#pragma unroll
    for (int mt = 0; mt < 4; mt++) {
        long long ra = bm + wm + mt * 16 + mrow;
        long long rb = ra + 8;
#pragma unroll
        for (int nt = 0; nt < 8; nt++) {
            long long col = bn + wn + nt * 8 + ncol;
            float b0 = 0.0f, b1 = 0.0f;
            if (bias) { b0 = bias[col]; b1 = bias[col + 1]; }
            float o0 = acc[mt][nt][0] + b0, o1 = acc[mt][nt][1] + b1;
            float o2 = acc[mt][nt][2] + b0, o3 = acc[mt][nt][3] + b1;
            if (relu) {
                o0 = fmaxf(o0, 0.0f); o1 = fmaxf(o1, 0.0f);
                o2 = fmaxf(o2, 0.0f); o3 = fmaxf(o3, 0.0f);
            }
            if (Cf) {
                *(float2*)(Cf + ra * ldc + col) = make_float2(o0, o1);
                *(float2*)(Cf + rb * ldc + col) = make_float2(o2, o3);
            }
            if (Chi) {
                __nv_bfloat16 h0 = __float2bfloat16_rn(o0);
                __nv_bfloat16 h1 = __float2bfloat16_rn(o1);
                __nv_bfloat16 h2 = __float2bfloat16_rn(o2);
                __nv_bfloat16 h3 = __float2bfloat16_rn(o3);
                *(uint32_t*)(Chi + ra * ldc + col) = pk2(h0, h1);
                *(uint32_t*)(Chi + rb * ldc + col) = pk2(h2, h3);
                *(uint32_t*)(Clo + ra * ldc + col) =
                    pk2(__float2bfloat16_rn(o0 - __bfloat162float(h0)),
                        __float2bfloat16_rn(o1 - __bfloat162float(h1)));
                *(uint32_t*)(Clo + rb * ldc + col) =
                    pk2(__float2bfloat16_rn(o2 - __bfloat162float(h2)),
                        __float2bfloat16_rn(o3 - __bfloat162float(h3)));
            }
        }
    }
}

// ---------------------------------------------------------------------------
// conv_split: fp32 -> bf16 hi/lo arrays
// ---------------------------------------------------------------------------
__global__ __launch_bounds__(256)
void conv_split(const float4* __restrict__ x, uint2* __restrict__ hi,
                uint2* __restrict__ lo, size_t n4)
{
    size_t i = (size_t)blockIdx.x * 256 + threadIdx.x;
    if (i >= n4) return;
    float4 v = x[i];
    __nv_bfloat16 h0 = __float2bfloat16_rn(v.x);
    __nv_bfloat16 h1 = __float2bfloat16_rn(v.y);
    __nv_bfloat16 h2 = __float2bfloat16_rn(v.z);
    __nv_bfloat16 h3 = __float2bfloat16_rn(v.w);
    hi[i] = make_uint2(pk2(h0, h1), pk2(h2, h3));
    lo[i] = make_uint2(
        pk2(__float2bfloat16_rn(v.x - __bfloat162float(h0)),
            __float2bfloat16_rn(v.y - __bfloat162float(h1))),
        pk2(__float2bfloat16_rn(v.z - __bfloat162float(h2)),
            __float2bfloat16_rn(v.w - __bfloat162float(h3))));
}

// ---------------------------------------------------------------------------
// transpose 1024x1024 fp32 -> bf16 hi/lo split, z selects matrix
// ---------------------------------------------------------------------------
__global__ __launch_bounds__(256)
void tr1024_split(const float* __restrict__ in, __nv_bfloat16* __restrict__ hi,
                  __nv_bfloat16* __restrict__ lo)
{
    __shared__ float t[32][33];
    in += (size_t)blockIdx.z * DD * DD;
    hi += (size_t)blockIdx.z * DD * DD;
    lo += (size_t)blockIdx.z * DD * DD;
    int x = blockIdx.x * 32 + threadIdx.x;
    int y = blockIdx.y * 32 + threadIdx.y;
#pragma unroll
    for (int i = 0; i < 4; i++)
        t[threadIdx.y + 8 * i][threadIdx.x] = in[(size_t)(y + 8 * i) * DD + x];
    __syncthreads();
    int x2 = blockIdx.y * 32 + threadIdx.x;
    int y2 = blockIdx.x * 32 + threadIdx.y;
#pragma unroll
    for (int i = 0; i < 4; i++) {
        float v = t[threadIdx.x][threadIdx.y + 8 * i];
        __nv_bfloat16 hv = __float2bfloat16_rn(v);
        size_t o = (size_t)(y2 + 8 * i) * DD + x2;
        hi[o] = hv;
        lo[o] = __float2bfloat16_rn(v - __bfloat162float(hv));
    }
}

// wv[k] = sum_e bq[e] * Wk[e,k]
__global__ void vec_kernel(const float* __restrict__ in_w,
                           const float* __restrict__ in_b,
                           float* __restrict__ wv)
{
    int k = blockIdx.x * 256 + threadIdx.x;
    const float* wkm = in_w + (size_t)DD * DD;
    const float* bq = in_b;
    float sv = 0.0f;
    for (int e = 0; e < DD; e++) sv += bq[e] * wkm[(size_t)e * DD + k];
    wv[k] = sv;
}

// ---------------------------------------------------------------------------
// attention: scores[s,t] = (t1[b,s].q[b,t] + gv[t]) / 32, softmax over t
// ---------------------------------------------------------------------------
__global__ __launch_bounds__(256)
void attn_kernel(const float* __restrict__ q, const float* __restrict__ t1,
                 const float* __restrict__ wv, float* __restrict__ attn)
{
    int b = blockIdx.x;
    __shared__ float sq[32 * 65];
    __shared__ float st[32 * 65];
    __shared__ float ssc[32 * 33];
    __shared__ float swv[64];
    __shared__ float gvp[8][33];
    const float* qb = q  + (size_t)b * SS * DD;
    const float* tbp = t1 + (size_t)b * SS * DD;
    int tid = threadIdx.x;
    int t = tid & 31, s0 = tid >> 5;
    float acc0 = 0, acc1 = 0, acc2 = 0, acc3 = 0, gvacc = 0;

    for (int kc = 0; kc < DD; kc += 64) {
        if (tid < 64) swv[tid] = wv[kc + tid];
        for (int i = tid; i < 32 * 16; i += 256) {
            int r = i >> 4, c4 = (i & 15) * 4;
            float4 a = *(const float4*)(qb + (size_t)r * DD + kc + c4);
            float4 v = *(const float4*)(tbp + (size_t)r * DD + kc + c4);
            sq[r * 65 + c4 + 0] = a.x; sq[r * 65 + c4 + 1] = a.y;
            sq[r * 65 + c4 + 2] = a.z; sq[r * 65 + c4 + 3] = a.w;
            st[r * 65 + c4 + 0] = v.x; st[r * 65 + c4 + 1] = v.y;
            st[r * 65 + c4 + 2] = v.z; st[r * 65 + c4 + 3] = v.w;
        }
        __syncthreads();
#pragma unroll 8
        for (int kk = 0; kk < 64; kk++) {
            float rq = sq[t * 65 + kk];
            acc0 += st[(s0 +  0) * 65 + kk] * rq;
            acc1 += st[(s0 +  8) * 65 + kk] * rq;
            acc2 += st[(s0 + 16) * 65 + kk] * rq;
            acc3 += st[(s0 + 24) * 65 + kk] * rq;
        }
#pragma unroll
        for (int j = 0; j < 8; j++)
            gvacc += sq[t * 65 + s0 * 8 + j] * swv[s0 * 8 + j];
        __syncthreads();
    }
    gvp[s0][t] = gvacc;
    __syncthreads();
    if (s0 == 0) {
        float s = 0.0f;
#pragma unroll
        for (int j = 0; j < 8; j++) s += gvp[j][t];
        gvp[0][t] = s;
    }
    __syncthreads();
    float vv = gvp[0][t];
    const float sc = 1.0f / 32.0f;
    ssc[(s0 +  0) * 33 + t] = (acc0 + vv) * sc;
    ssc[(s0 +  8) * 33 + t] = (acc1 + vv) * sc;
    ssc[(s0 + 16) * 33 + t] = (acc2 + vv) * sc;
    ssc[(s0 + 24) * 33 + t] = (acc3 + vv) * sc;
    __syncthreads();
    if (tid < 32) {
        float mx = -1e30f;
        for (int j = 0; j < 32; j++) mx = fmaxf(mx, ssc[tid * 33 + j]);
        float sum = 0.0f;
        for (int j = 0; j < 32; j++) {
            float e = expf(ssc[tid * 33 + j] - mx);
            ssc[tid * 33 + j] = e; sum += e;
        }
        float inv = 1.0f / sum;
        for (int j = 0; j < 32; j++)
            attn[(size_t)b * SS * SS + tid * 32 + j] = ssc[tid * 33 + j] * inv;
    }
}

// ---------------------------------------------------------------------------
// classifier scalar + softmax halves -> d_a/d_v (out tail + scratch)
// ---------------------------------------------------------------------------
__global__ __launch_bounds__(512)
void cls_head_kernel(const float* __restrict__ h, const float* __restrict__ w2,
                     const float* __restrict__ b2, float* __restrict__ dav,
                     float* __restrict__ out_d)
{
    int b = blockIdx.x;
    __shared__ float sd[32];
    int w = threadIdx.x >> 5, lane = threadIdx.x & 31;
    for (int s = w; s < SS; s += 16) {
        const float* hr = h + ((size_t)b * SS + s) * HH;
        const float* wr = w2 + (size_t)s * HH;
        float acc = 0.0f;
        for (int k = lane; k < HH; k += 32) acc += hr[k] * wr[k];
#pragma unroll
        for (int o = 16; o; o >>= 1) acc += __shfl_down_sync(0xffffffffu, acc, o);
        if (lane == 0) sd[s] = fmaxf(acc + b2[s], 0.0f);
    }
    __syncthreads();
    if (threadIdx.x < 2) {
        int off = threadIdx.x * PP;
        float mx = -1e30f;
        for (int j = 0; j < PP; j++) mx = fmaxf(mx, sd[off + j]);
        float sum = 0.0f;
        float e[PP];
        for (int j = 0; j < PP; j++) { e[j] = expf(sd[off + j] - mx); sum += e[j]; }
        float inv = 1.0f / sum;
        float* outp = out_d + (size_t)threadIdx.x * BB * PP + (size_t)b * PP;
        for (int j = 0; j < PP; j++) {
            float val = e[j] * inv;
            dav[b * SS + off + j] = val;
            outp[j] = val;
        }
    }
}

// ---------------------------------------------------------------------------
// q-space mix -> avmix bf16 hi/lo
// ---------------------------------------------------------------------------
__global__ __launch_bounds__(128)
void combine_kernel(const float* __restrict__ attn, const float* __restrict__ q,
                    const float* __restrict__ dav,
                    __nv_bfloat16* __restrict__ mxh, __nv_bfloat16* __restrict__ mxl)
{
    int b = blockIdx.x;
    __shared__ float sat[SS * SS];
    __shared__ float wa[SS], wvv[SS];
    int tid = threadIdx.x;
    for (int i = tid; i < SS * SS; i += 128) sat[i] = attn[(size_t)b * SS * SS + i];
    __syncthreads();
    if (tid < SS) {
        float a = 0.0f, v = 0.0f;
        for (int s = 0; s < PP; s++) {
            a += dav[b * SS + s]      * sat[s * SS + tid];
            v += dav[b * SS + PP + s] * sat[(PP + s) * SS + tid];
        }
        wa[tid] = a; wvv[tid] = v;
    }
    __syncthreads();
    const float* qb = q + (size_t)b * SS * DD;
    for (int d0 = tid * 2; d0 < DD; d0 += 256) {
        float a0 = 0, a1 = 0, v0 = 0, v1 = 0;
#pragma unroll
        for (int t = 0; t < SS; t++) {
            float2 x = *(const float2*)(qb + (size_t)t * DD + d0);
            a0 += wa[t] * x.x; a1 += wa[t] * x.y;
            v0 += wvv[t] * x.x; v1 += wvv[t] * x.y;
        }
        size_t oa = (size_t)b * DD + d0;
        size_t ov = ((size_t)BB + b) * DD + d0;
        __nv_bfloat16 h0 = __float2bfloat16_rn(a0), h1 = __float2bfloat16_rn(a1);
        *(uint32_t*)(mxh + oa) = pk2(h0, h1);
        *(uint32_t*)(mxl + oa) = pk2(__float2bfloat16_rn(a0 - __bfloat162float(h0)),
                                     __float2bfloat16_rn(a1 - __bfloat162float(h1)));
        h0 = __float2bfloat16_rn(v0); h1 = __float2bfloat16_rn(v1);
        *(uint32_t*)(mxh + ov) = pk2(h0, h1);
        *(uint32_t*)(mxl + ov) = pk2(__float2bfloat16_rn(v0 - __bfloat162float(h0)),
                                     __float2bfloat16_rn(v1 - __bfloat162float(h1)));
    }
}

// ---------------------------------------------------------------------------
// split_avg: favf (audio, video) -> favs split (fusion, audio, video)
// ---------------------------------------------------------------------------
__global__ __launch_bounds__(256)
void split_avg(const float* __restrict__ favf,
               __nv_bfloat16* __restrict__ fh, __nv_bfloat16* __restrict__ fl)
{
    size_t i = ((size_t)blockIdx.x * 256 + threadIdx.x) * 2;
    float2 a = *(const float2*)(favf + i);
    float2 v = *(const float2*)(favf + (size_t)BB * DD + i);
    float f0 = 0.5f * (a.x + v.x), f1 = 0.5f * (a.y + v.y);
#define WSPL(base, x0, x1) do {                                               \
    __nv_bfloat16 h0 = __float2bfloat16_rn(x0), h1 = __float2bfloat16_rn(x1); \
    *(uint32_t*)(fh + (base)) = pk2(h0, h1);                                  \
    *(uint32_t*)(fl + (base)) = pk2(                                          \
        __float2bfloat16_rn((x0) - __bfloat162float(h0)),                     \
        __float2bfloat16_rn((x1) - __bfloat162float(h1)));                    \
} while (0)
    WSPL(i, f0, f1);
    WSPL((size_t)BB * DD + i, a.x, a.y);
    WSPL((size_t)2 * BB * DD + i, v.x, v.y);
#undef WSPL
}

// ---------------------------------------------------------------------------
// LayerNorm(512) + ReLU per row
// ---------------------------------------------------------------------------
__global__ __launch_bounds__(128)
void ln_kernel(const float* __restrict__ x, const float* __restrict__ g,
               const float* __restrict__ be, float* __restrict__ out)
{
    int row = blockIdx.x;
    const float* xr = x + (size_t)row * FF;
    int tid = threadIdx.x;
    __shared__ float sm[4];
    float v[4];
    float s = 0.0f;
#pragma unroll
    for (int i = 0; i < 4; i++) { v[i] = xr[tid + 128 * i]; s += v[i]; }
#pragma unroll
    for (int o = 16; o; o >>= 1) s += __shfl_down_sync(0xffffffffu, s, o);
    if ((tid & 31) == 0) sm[tid >> 5] = s;
    __syncthreads();
    float mu = (sm[0] + sm[1] + sm[2] + sm[3]) * (1.0f / FF);
    __syncthreads();
    float qv = 0.0f;
#pragma unroll
    for (int i = 0; i < 4; i++) { float d = v[i] - mu; qv += d * d; }
#pragma unroll
    for (int o = 16; o; o >>= 1) qv += __shfl_down_sync(0xffffffffu, qv, o);
    if ((tid & 31) == 0) sm[tid >> 5] = qv;
    __syncthreads();
    float var = (sm[0] + sm[1] + sm[2] + sm[3]) * (1.0f / FF);
    float rstd = rsqrtf(var + 1e-5f);
    float* orow = out + (size_t)row * FF;
#pragma unroll
    for (int i = 0; i < 4; i++) {
        int c = tid + 128 * i;
        float y = (v[i] - mu) * rstd * g[c] + be[c];
        orow[c] = fmaxf(y, 0.0f);
    }
}

// ---------------------------------------------------------------------------
extern "C" void kernel_launch(void* const* d_in, const int* in_sizes, int n_in,
                              void* d_out, int out_size)
{
    const float* q      = (const float*)d_in[0];
    const float* in_w   = (const float*)d_in[1];
    const float* in_b   = (const float*)d_in[2];
    const float* out_w  = (const float*)d_in[3];
    const float* out_b  = (const float*)d_in[4];
    const float* cls_w1 = (const float*)d_in[5];
    const float* cls_b1 = (const float*)d_in[6];
    const float* cls_w2 = (const float*)d_in[7];
    const float* cls_b2 = (const float*)d_in[8];
    const float* fus_w  = (const float*)d_in[9];
    const float* fus_b  = (const float*)d_in[10];
    const float* fus_g  = (const float*)d_in[11];
    const float* fus_be = (const float*)d_in[12];
    const float* pa_w   = (const float*)d_in[13];
    const float* pa_b   = (const float*)d_in[14];
    const float* pa_g   = (const float*)d_in[15];
    const float* pa_be  = (const float*)d_in[16];
    const float* pv_w   = (const float*)d_in[17];
    const float* pv_b   = (const float*)d_in[18];
    const float* pv_g   = (const float*)d_in[19];
    const float* pv_be  = (const float*)d_in[20];
    float* out = (float*)d_out;

    float* sp = nullptr;
    cudaGetSymbolAddress((void**)&sp, g_scratch);

    float* t1    = sp + OF_T1;
    float* h     = sp + OF_H;
    float* attn  = sp + OF_ATTN;
    float* dav   = sp + OF_DAV;
    float* headb = sp + OF_HEAD;
    float* favf  = sp + OF_FAVF;
    float* wv    = sp + OF_WV;

    typedef __nv_bfloat16 bf;
    bf* qhi  = (bf*)(sp + OF_QS);     bf* qlo  = qhi + E_Q;
    bf* w1hi = (bf*)(sp + OF_W1S);    bf* w1lo = w1hi + E_W1;
    bf* mthi = (bf*)(sp + OF_MTS);    bf* mtlo = mthi + E_MT;
    bf* wthi = (bf*)(sp + OF_WTS);    bf* wtlo = wthi + E_WT;
    bf* wvwhi = (bf*)(sp + OF_WVWS);  bf* wvwlo = wvwhi + E_WVW;
    bf* owhi = (bf*)(sp + OF_OUTWS);  bf* owlo = owhi + E_OUTW;
    bf* hwhi = (bf*)(sp + OF_HWS);    bf* hwlo = hwhi + E_HW;
    bf* mxhi = (bf*)(sp + OF_AVMIXS); bf* mxlo = mxhi + E_AVMIX;
    bf* aphi = (bf*)(sp + OF_AVPRES); bf* aplo = aphi + E_AVPRE;
    bf* fvhi = (bf*)(sp + OF_FAVS);   bf* fvlo = fvhi + E_FAV;

    const float* wv_w = in_w + (size_t)2 * DD * DD;
    const float* bv = in_b + 2 * DD;

    const unsigned SMB = N_STAGES * STAGE_BYTES;
    cudaFuncSetAttribute(mma_gemm, cudaFuncAttributeMaxDynamicSharedMemorySize, SMB);

    // ---- prep: split conversions ----
    conv_split<<<(unsigned)(E_Q / 4 / 256), 256>>>((const float4*)q, (uint2*)qhi, (uint2*)qlo, E_Q / 4);
    conv_split<<<(unsigned)(E_W1 / 4 / 256), 256>>>((const float4*)cls_w1, (uint2*)w1hi, (uint2*)w1lo, E_W1 / 4);
    conv_split<<<(unsigned)(E_WVW / 4 / 256), 256>>>((const float4*)wv_w, (uint2*)wvwhi, (uint2*)wvwlo, E_WVW / 4);
    conv_split<<<(unsigned)(E_OUTW / 4 / 256), 256>>>((const float4*)out_w, (uint2*)owhi, (uint2*)owlo, E_OUTW / 4);
    size_t eh = (size_t)FF * DD;
    conv_split<<<(unsigned)(eh / 4 / 256), 256>>>((const float4*)fus_w, (uint2*)hwhi, (uint2*)hwlo, eh / 4);
    conv_split<<<(unsigned)(eh / 4 / 256), 256>>>((const float4*)pa_w, (uint2*)(hwhi + eh), (uint2*)(hwlo + eh), eh / 4);
    conv_split<<<(unsigned)(eh / 4 / 256), 256>>>((const float4*)pv_w, (uint2*)(hwhi + 2 * eh), (uint2*)(hwlo + 2 * eh), eh / 4);
    tr1024_split<<<dim3(32, 32, 2), dim3(32, 8)>>>(in_w, wthi, wtlo);
    vec_kernel<<<4, 256>>>(in_w, in_b, wv);

    bf* wqthi = wthi;                     bf* wqtlo = wtlo;
    bf* wkthi = wthi + (size_t)DD * DD;   bf* wktlo = wtlo + (size_t)DD * DD;

    // ---- Mt[n,k] = sum_e WkT[n,e]*WqT[k,e] -> split ----
    mma_gemm<<<dim3(4, 8, 1), 256, SMB>>>(
        wkthi, wktlo, DD, 0, wqthi, wqtlo, DD, 0, nullptr, 0,
        nullptr, mthi, mtlo, DD, 0, DD, 0);
    // ---- t1 = q @ M -> fp32 ----
    mma_gemm<<<dim3(4, 512, 1), 256, SMB>>>(
        qhi, qlo, DD, 0, mthi, mtlo, DD, 0, nullptr, 0,
        t1, nullptr, nullptr, DD, 0, DD, 0);
    // ---- h = relu(q @ W1[s]^T + b1[s]) -> fp32 ----
    mma_gemm<<<dim3(2, 16, 32), 256, SMB>>>(
        qhi, qlo, SS * DD, DD, w1hi, w1lo, DD, (long long)HH * DD, cls_b1, HH,
        h, nullptr, nullptr, SS * HH, HH, DD, 1);
    // ---- attention (fused gv) ----
    attn_kernel<<<BB, 256>>>(q, t1, wv, attn);
    // ---- classifier head ----
    cls_head_kernel<<<BB, 512>>>(h, cls_w2, cls_b2, dav, out + (size_t)3 * BB * FF);
    // ---- q-space mix -> avmix split ----
    combine_kernel<<<BB, 128>>>(attn, q, dav, mxhi, mxlo);
    // ---- avpre = avmix @ Wv^T + bv -> split ----
    mma_gemm<<<dim3(4, 32, 1), 256, SMB>>>(
        mxhi, mxlo, DD, 0, wvwhi, wvwlo, DD, 0, bv, 0,
        nullptr, aphi, aplo, DD, 0, DD, 0);
    // ---- audio/video = avpre @ out_w^T + out_b -> fp32 favf ----
    mma_gemm<<<dim3(4, 32, 1), 256, SMB>>>(
        aphi, aplo, DD, 0, owhi, owlo, DD, 0, out_b, 0,
        favf, nullptr, nullptr, DD, 0, DD, 0);
    // ---- fusion avg + split all three segments ----
    split_avg<<<(BB * DD) / 512, 256>>>(favf, fvhi, fvlo);
    // ---- projector heads -> fp32 headb ----
    mma_gemm<<<dim3(2, 16, 1), 256, SMB>>>(
        fvhi, fvlo, DD, 0, hwhi, hwlo, DD, 0, fus_b, 0,
        headb, nullptr, nullptr, FF, 0, DD, 0);
    mma_gemm<<<dim3(2, 16, 1), 256, SMB>>>(
        fvhi + (size_t)BB * DD, fvlo + (size_t)BB * DD, DD, 0,
        hwhi + eh, hwlo + eh, DD, 0, pa_b, 0,
        headb + (size_t)BB * FF, nullptr, nullptr, FF, 0, DD, 0);
    mma_gemm<<<dim3(2, 16, 1), 256, SMB>>>(
        fvhi + (size_t)2 * BB * DD, fvlo + (size_t)2 * BB * DD, DD, 0,
        hwhi + 2 * eh, hwlo + 2 * eh, DD, 0, pv_b, 0,
        headb + (size_t)2 * BB * FF, nullptr, nullptr, FF, 0, DD, 0);
    // ---- LayerNorm + ReLU ----
    ln_kernel<<<BB, 128>>>(headb, fus_g, fus_be, out);
    ln_kernel<<<BB, 128>>>(headb + (size_t)BB * FF, pa_g, pa_be, out + (size_t)BB * FF);
    ln_kernel<<<BB, 128>>>(headb + (size_t)2 * BB * FF, pv_g, pv_be, out + (size_t)2 * BB * FF);
}

// round 8
// speedup vs baseline: 1.1398x; 1.1398x over previous
#include <cuda_runtime.h>
#include <cuda_bf16.h>
#include <stdint.h>
#include <math.h>

// Problem dims
#define BB 2048
#define SS 32
#define DD 1024
#define PP 16
#define FF 512
#define HH 512

// ---------------- scratch layout (single __device__ array) ------------------
#define N_T1    ((size_t)BB * SS * DD)
#define N_H     ((size_t)BB * SS * HH)
#define N_ATTN  ((size_t)BB * SS * SS)
#define N_GV    ((size_t)BB * SS)
#define N_DAV   ((size_t)BB * SS)
#define N_AVMIX ((size_t)2 * BB * DD)
#define N_AVPRE ((size_t)2 * BB * DD)
#define N_FAV   ((size_t)3 * BB * DD)
#define N_HEAD  ((size_t)3 * BB * FF)
#define N_MT    ((size_t)DD * DD)
#define N_WT    ((size_t)2 * DD * DD)

#define OF_T1    ((size_t)0)
#define OF_H     (OF_T1 + N_T1)
#define OF_ATTN  (OF_H + N_H)
#define OF_GV    (OF_ATTN + N_ATTN)
#define OF_DAV   (OF_GV + N_GV)
#define OF_AVMIX (OF_DAV + N_DAV)
#define OF_AVPRE (OF_AVMIX + N_AVMIX)
#define OF_FAV   (OF_AVPRE + N_AVPRE)
#define OF_HEAD  (OF_FAV + N_FAV)
#define OF_MT    (OF_HEAD + N_HEAD)
#define OF_WT    (OF_MT + N_MT)
#define OF_WV    (OF_WT + N_WT)
#define SCRATCH_FLOATS (OF_WV + 1024)

__device__ float g_scratch[SCRATCH_FLOATS];

// ======================= helpers ===========================================
__device__ __forceinline__ uint32_t smem_u32(const void* p) {
    uint32_t a;
    asm("{ .reg .u64 t; cvta.to.shared.u64 t, %1; cvt.u32.u64 %0, t; }"
        : "=r"(a) : "l"(p));
    return a;
}
__device__ __forceinline__ uint32_t pk2(__nv_bfloat16 a, __nv_bfloat16 b) {
    __nv_bfloat162 t = __halves2bfloat162(a, b);
    return *reinterpret_cast<uint32_t*>(&t);
}
__device__ __forceinline__ uint32_t f2tf32(float x) {
    uint32_t u;
    asm("cvt.rna.tf32.f32 %0, %1;" : "=r"(u) : "f"(x));
    return u;
}

#define LDSM_X4(r0, r1, r2, r3, addr) \
    asm volatile("ldmatrix.sync.aligned.m8n8.x4.shared.b16 {%0,%1,%2,%3}, [%4];" \
                 : "=r"(r0), "=r"(r1), "=r"(r2), "=r"(r3) : "r"(addr))

#define MMA16816(d, a, b0, b1) \
    asm volatile("mma.sync.aligned.m16n8k16.row.col.f32.bf16.bf16.f32 " \
                 "{%0,%1,%2,%3}, {%4,%5,%6,%7}, {%8,%9}, {%0,%1,%2,%3};" \
                 : "+f"((d)[0]), "+f"((d)[1]), "+f"((d)[2]), "+f"((d)[3]) \
                 : "r"((a)[0]), "r"((a)[1]), "r"((a)[2]), "r"((a)[3]), \
                   "r"(b0), "r"(b1))

#define MMATF32(d, a, b0, b1) \
    asm volatile("mma.sync.aligned.m16n8k8.row.col.f32.tf32.tf32.f32 " \
                 "{%0,%1,%2,%3}, {%4,%5,%6,%7}, {%8,%9}, {%0,%1,%2,%3};" \
                 : "+f"((d)[0]), "+f"((d)[1]), "+f"((d)[2]), "+f"((d)[3]) \
                 : "r"((a)[0]), "r"((a)[1]), "r"((a)[2]), "r"((a)[3]), \
                   "r"(b0), "r"(b1))

// ===========================================================================
// (A) Split-bf16 3-pass NT GEMM (PROVEN R4 kernel) — used for small GEMMs.
// fp32 in/out, internal bf16 hi/lo x 3 passes. Tile 128x128, BK=32, 256 thr.
// ===========================================================================
#define AST 80
#define PL_AHI 0
#define PL_ALO 10240
#define PL_BHI 20480
#define PL_BLO 30720

__global__ __launch_bounds__(256)
void mma_gemm(const float* __restrict__ A, long long lda, long long zA,
              const float* __restrict__ Bt, long long ldb, long long zB,
              const float* __restrict__ bias, long long zBias,
              float* __restrict__ C, long long ldc, long long zC,
              int K, int relu)
{
    __shared__ __align__(16) char smem[40960];
    const uint32_t sb = smem_u32(smem);

    A  += (long long)blockIdx.z * zA;
    Bt += (long long)blockIdx.z * zB;
    C  += (long long)blockIdx.z * zC;
    if (bias) bias += (long long)blockIdx.z * zBias;

    const int tid = threadIdx.x;
    const int wid = tid >> 5, lid = tid & 31;
    const long long bm = (long long)blockIdx.y * 128;
    const long long bn = (long long)blockIdx.x * 128;
    const int wm = (wid & 1) * 64;
    const int wn = (wid >> 1) * 32;

    float acc[4][4][4];
#pragma unroll
    for (int mt = 0; mt < 4; mt++)
#pragma unroll
        for (int nt = 0; nt < 4; nt++)
#pragma unroll
            for (int r = 0; r < 4; r++) acc[mt][nt][r] = 0.0f;

    const int q = lid >> 3, qr = lid & 7;

    float4 pa[4], pb[4];
#pragma unroll
    for (int i = 0; i < 4; i++) {
        int idx = i * 256 + tid;
        int r = idx >> 3, c4 = idx & 7;
        pa[i] = *(const float4*)(A  + (bm + r) * lda + c4 * 4);
        pb[i] = *(const float4*)(Bt + (bn + r) * ldb + c4 * 4);
    }

    for (int k0 = 0; k0 < K; k0 += 32) {
#pragma unroll
        for (int i = 0; i < 4; i++) {
            int idx = i * 256 + tid;
            int r = idx >> 3, c4 = idx & 7;
            float4 v = pa[i];
            __nv_bfloat16 h0 = __float2bfloat16_rn(v.x);
            __nv_bfloat16 h1 = __float2bfloat16_rn(v.y);
            __nv_bfloat16 h2 = __float2bfloat16_rn(v.z);
            __nv_bfloat16 h3 = __float2bfloat16_rn(v.w);
            __nv_bfloat16 l0 = __float2bfloat16_rn(v.x - __bfloat162float(h0));
            __nv_bfloat16 l1 = __float2bfloat16_rn(v.y - __bfloat162float(h1));
            __nv_bfloat16 l2 = __float2bfloat16_rn(v.z - __bfloat162float(h2));
            __nv_bfloat16 l3 = __float2bfloat16_rn(v.w - __bfloat162float(h3));
            *(uint2*)(smem + PL_AHI + r * AST + c4 * 8) = make_uint2(pk2(h0, h1), pk2(h2, h3));
            *(uint2*)(smem + PL_ALO + r * AST + c4 * 8) = make_uint2(pk2(l0, l1), pk2(l2, l3));
            v = pb[i];
            h0 = __float2bfloat16_rn(v.x); h1 = __float2bfloat16_rn(v.y);
            h2 = __float2bfloat16_rn(v.z); h3 = __float2bfloat16_rn(v.w);
            l0 = __float2bfloat16_rn(v.x - __bfloat162float(h0));
            l1 = __float2bfloat16_rn(v.y - __bfloat162float(h1));
            l2 = __float2bfloat16_rn(v.z - __bfloat162float(h2));
            l3 = __float2bfloat16_rn(v.w - __bfloat162float(h3));
            *(uint2*)(smem + PL_BHI + r * AST + c4 * 8) = make_uint2(pk2(h0, h1), pk2(h2, h3));
            *(uint2*)(smem + PL_BLO + r * AST + c4 * 8) = make_uint2(pk2(l0, l1), pk2(l2, l3));
        }
        __syncthreads();

        if (k0 + 32 < K) {
#pragma unroll
            for (int i = 0; i < 4; i++) {
                int idx = i * 256 + tid;
                int r = idx >> 3, c4 = idx & 7;
                pa[i] = *(const float4*)(A  + (bm + r) * lda + k0 + 32 + c4 * 4);
                pb[i] = *(const float4*)(Bt + (bn + r) * ldb + k0 + 32 + c4 * 4);
            }
        }

#pragma unroll
        for (int kk = 0; kk < 32; kk += 16) {
            uint32_t ah[4][4], al[4][4], bh[2][4], bl[2][4];
#pragma unroll
            for (int mt = 0; mt < 4; mt++) {
                uint32_t row = wm + mt * 16 + (q & 1) * 8 + qr;
                uint32_t off = row * AST + kk * 2 + (q >> 1) * 16;
                LDSM_X4(ah[mt][0], ah[mt][1], ah[mt][2], ah[mt][3], sb + PL_AHI + off);
                LDSM_X4(al[mt][0], al[mt][1], al[mt][2], al[mt][3], sb + PL_ALO + off);
            }
#pragma unroll
            for (int nt2 = 0; nt2 < 2; nt2++) {
                uint32_t row = wn + nt2 * 16 + (q >> 1) * 8 + qr;
                uint32_t off = row * AST + kk * 2 + (q & 1) * 16;
                LDSM_X4(bh[nt2][0], bh[nt2][1], bh[nt2][2], bh[nt2][3], sb + PL_BHI + off);
                LDSM_X4(bl[nt2][0], bl[nt2][1], bl[nt2][2], bl[nt2][3], sb + PL_BLO + off);
            }
#pragma unroll
            for (int mt = 0; mt < 4; mt++) {
#pragma unroll
                for (int nt = 0; nt < 4; nt++) {
                    int n2 = nt >> 1, o = (nt & 1) * 2;
                    MMA16816(acc[mt][nt], ah[mt], bh[n2][o], bh[n2][o + 1]);
                    MMA16816(acc[mt][nt], ah[mt], bl[n2][o], bl[n2][o + 1]);
                    MMA16816(acc[mt][nt], al[mt], bh[n2][o], bh[n2][o + 1]);
                }
            }
        }
        __syncthreads();
    }

    const int mrow = lid >> 2, ncol = (lid & 3) * 2;
#pragma unroll
    for (int mt = 0; mt < 4; mt++) {
        long long r0 = bm + wm + mt * 16 + mrow;
        long long r1 = r0 + 8;
#pragma unroll
        for (int nt = 0; nt < 4; nt++) {
            long long col = bn + wn + nt * 8 + ncol;
            float b0 = 0.0f, b1 = 0.0f;
            if (bias) { b0 = bias[col]; b1 = bias[col + 1]; }
            float o0 = acc[mt][nt][0] + b0, o1 = acc[mt][nt][1] + b1;
            float o2 = acc[mt][nt][2] + b0, o3 = acc[mt][nt][3] + b1;
            if (relu) {
                o0 = fmaxf(o0, 0.0f); o1 = fmaxf(o1, 0.0f);
                o2 = fmaxf(o2, 0.0f); o3 = fmaxf(o3, 0.0f);
            }
            *(float2*)(C + r0 * ldc + col) = make_float2(o0, o1);
            *(float2*)(C + r1 * ldc + col) = make_float2(o2, o3);
        }
    }
}

// ===========================================================================
// (B) tf32 single-pass NT GEMM — used for the two big GEMMs (t1, h).
//   C[m,n] = sum_k A[m,k]*Bt[n,k] (+bias[n]) (+relu), fp32 in/out, err ~3e-4
// Tile 128x128, BK=32, 256 threads (8 warps, warp tile 64x32).
// smem rows stride 36 floats -> conflict-free fragment LDS (bank = 4g+tig).
// ===========================================================================
#define TST 36

__global__ __launch_bounds__(256)
void tf32_gemm(const float* __restrict__ A, long long lda, long long zA,
               const float* __restrict__ Bt, long long ldb, long long zB,
               const float* __restrict__ bias, long long zBias,
               float* __restrict__ C, long long ldc, long long zC,
               int K, int relu)
{
    __shared__ __align__(16) float sA[128 * TST];
    __shared__ __align__(16) float sB[128 * TST];

    A  += (long long)blockIdx.z * zA;
    Bt += (long long)blockIdx.z * zB;
    C  += (long long)blockIdx.z * zC;
    if (bias) bias += (long long)blockIdx.z * zBias;

    const int tid = threadIdx.x;
    const int wid = tid >> 5, lid = tid & 31;
    const long long bm = (long long)blockIdx.y * 128;
    const long long bn = (long long)blockIdx.x * 128;
    const int wm = (wid & 1) * 64;
    const int wn = (wid >> 1) * 32;
    const int g = lid >> 2, tig = lid & 3;

    float acc[4][4][4];
#pragma unroll
    for (int mt = 0; mt < 4; mt++)
#pragma unroll
        for (int nt = 0; nt < 4; nt++)
#pragma unroll
            for (int r = 0; r < 4; r++) acc[mt][nt][r] = 0.0f;

    float4 pa[4], pb[4];
#pragma unroll
    for (int i = 0; i < 4; i++) {
        int idx = i * 256 + tid;
        int r = idx >> 3, c4 = idx & 7;
        pa[i] = *(const float4*)(A  + (bm + r) * lda + c4 * 4);
        pb[i] = *(const float4*)(Bt + (bn + r) * ldb + c4 * 4);
    }

    for (int k0 = 0; k0 < K; k0 += 32) {
        // store prefetched slab as tf32
#pragma unroll
        for (int i = 0; i < 4; i++) {
            int idx = i * 256 + tid;
            int r = idx >> 3, c4 = (idx & 7) * 4;
            float4 v = pa[i];
            uint4 t;
            t.x = f2tf32(v.x); t.y = f2tf32(v.y); t.z = f2tf32(v.z); t.w = f2tf32(v.w);
            *(uint4*)&sA[r * TST + c4] = t;
            v = pb[i];
            t.x = f2tf32(v.x); t.y = f2tf32(v.y); t.z = f2tf32(v.z); t.w = f2tf32(v.w);
            *(uint4*)&sB[r * TST + c4] = t;
        }
        __syncthreads();

        if (k0 + 32 < K) {
#pragma unroll
            for (int i = 0; i < 4; i++) {
                int idx = i * 256 + tid;
                int r = idx >> 3, c4 = idx & 7;
                pa[i] = *(const float4*)(A  + (bm + r) * lda + k0 + 32 + c4 * 4);
                pb[i] = *(const float4*)(Bt + (bn + r) * ldb + k0 + 32 + c4 * 4);
            }
        }

#pragma unroll
        for (int ks = 0; ks < 4; ks++) {
            uint32_t af[4][4], bf[4][2];
            const int cb = ks * 8 + tig;
#pragma unroll
            for (int mt = 0; mt < 4; mt++) {
                int r0 = wm + mt * 16 + g;
                af[mt][0] = __float_as_uint(sA[r0 * TST + cb]);
                af[mt][1] = __float_as_uint(sA[(r0 + 8) * TST + cb]);
                af[mt][2] = __float_as_uint(sA[r0 * TST + cb + 4]);
                af[mt][3] = __float_as_uint(sA[(r0 + 8) * TST + cb + 4]);
            }
#pragma unroll
            for (int nt = 0; nt < 4; nt++) {
                int n0 = wn + nt * 8 + g;
                bf[nt][0] = __float_as_uint(sB[n0 * TST + cb]);
                bf[nt][1] = __float_as_uint(sB[n0 * TST + cb + 4]);
            }
#pragma unroll
            for (int mt = 0; mt < 4; mt++)
#pragma unroll
                for (int nt = 0; nt < 4; nt++)
                    MMATF32(acc[mt][nt], af[mt], bf[nt][0], bf[nt][1]);
        }
        __syncthreads();
    }

    const int mrow = lid >> 2, ncol = (lid & 3) * 2;
#pragma unroll
    for (int mt = 0; mt < 4; mt++) {
        long long r0 = bm + wm + mt * 16 + mrow;
        long long r1 = r0 + 8;
#pragma unroll
        for (int nt = 0; nt < 4; nt++) {
            long long col = bn + wn + nt * 8 + ncol;
            float b0 = 0.0f, b1 = 0.0f;
            if (bias) { b0 = bias[col]; b1 = bias[col + 1]; }
            float o0 = acc[mt][nt][0] + b0, o1 = acc[mt][nt][1] + b1;
            float o2 = acc[mt][nt][2] + b0, o3 = acc[mt][nt][3] + b1;
            if (relu) {
                o0 = fmaxf(o0, 0.0f); o1 = fmaxf(o1, 0.0f);
                o2 = fmaxf(o2, 0.0f); o3 = fmaxf(o3, 0.0f);
            }
            *(float2*)(C + r0 * ldc + col) = make_float2(o0, o1);
            *(float2*)(C + r1 * ldc + col) = make_float2(o2, o3);
        }
    }
}

// ---------------------------------------------------------------------------
// transpose 1024x1024 fp32 (z selects matrix): out[i,j] = in[j,i]
// ---------------------------------------------------------------------------
__global__ __launch_bounds__(256)
void tr1024(const float* __restrict__ in, float* __restrict__ out)
{
    __shared__ float t[32][33];
    in  += (size_t)blockIdx.z * DD * DD;
    out += (size_t)blockIdx.z * DD * DD;
    int x = blockIdx.x * 32 + threadIdx.x;
    int y = blockIdx.y * 32 + threadIdx.y;
#pragma unroll
    for (int i = 0; i < 4; i++)
        t[threadIdx.y + 8 * i][threadIdx.x] = in[(size_t)(y + 8 * i) * DD + x];
    __syncthreads();
    int x2 = blockIdx.y * 32 + threadIdx.x;
    int y2 = blockIdx.x * 32 + threadIdx.y;
#pragma unroll
    for (int i = 0; i < 4; i++)
        out[(size_t)(y2 + 8 * i) * DD + x2] = t[threadIdx.x][threadIdx.y + 8 * i];
}

// wv[k] = sum_e bq[e] * Wk[e,k]
__global__ void vec_kernel(const float* __restrict__ in_w,
                           const float* __restrict__ in_b,
                           float* __restrict__ wv)
{
    int k = blockIdx.x * 256 + threadIdx.x;
    const float* wkm = in_w + (size_t)DD * DD;
    const float* bq = in_b;
    float sv = 0.0f;
    for (int e = 0; e < DD; e++) sv += bq[e] * wkm[(size_t)e * DD + k];
    wv[k] = sv;
}

// gv[b,s] = q[b,s,:] . wv
__global__ __launch_bounds__(1024)
void uv_kernel(const float* __restrict__ q, const float* __restrict__ wv,
               float* __restrict__ gv)
{
    int b = blockIdx.x;
    int w = threadIdx.x >> 5, lane = threadIdx.x & 31;
    const float* row = q + ((size_t)b * SS + w) * DD;
    float sv = 0.0f;
    for (int k = lane; k < DD; k += 32) sv += row[k] * wv[k];
#pragma unroll
    for (int o = 16; o; o >>= 1) sv += __shfl_down_sync(0xffffffffu, sv, o);
    if (lane == 0) gv[b * SS + w] = sv;
}

// ---------------------------------------------------------------------------
// attention: scores[s,t] = (t1[b,s].q[b,t] + gv[t]) / 32, softmax over t
// ---------------------------------------------------------------------------
__global__ __launch_bounds__(256)
void attn_kernel(const float* __restrict__ q, const float* __restrict__ t1,
                 const float* __restrict__ gv, float* __restrict__ attn)
{
    int b = blockIdx.x;
    __shared__ float sq[32 * 65];
    __shared__ float st[32 * 65];
    __shared__ float ssc[32 * 33];
    const float* qb = q  + (size_t)b * SS * DD;
    const float* tbp = t1 + (size_t)b * SS * DD;
    int tid = threadIdx.x;
    int t = tid & 31, s0 = tid >> 5;
    float acc0 = 0, acc1 = 0, acc2 = 0, acc3 = 0;

    for (int kc = 0; kc < DD; kc += 64) {
        for (int i = tid; i < 32 * 16; i += 256) {
            int r = i >> 4, c4 = (i & 15) * 4;
            float4 a = *(const float4*)(qb + (size_t)r * DD + kc + c4);
            float4 v = *(const float4*)(tbp + (size_t)r * DD + kc + c4);
            sq[r * 65 + c4 + 0] = a.x; sq[r * 65 + c4 + 1] = a.y;
            sq[r * 65 + c4 + 2] = a.z; sq[r * 65 + c4 + 3] = a.w;
            st[r * 65 + c4 + 0] = v.x; st[r * 65 + c4 + 1] = v.y;
            st[r * 65 + c4 + 2] = v.z; st[r * 65 + c4 + 3] = v.w;
        }
        __syncthreads();
#pragma unroll 8
        for (int kk = 0; kk < 64; kk++) {
            float rq = sq[t * 65 + kk];
            acc0 += st[(s0 +  0) * 65 + kk] * rq;
            acc1 += st[(s0 +  8) * 65 + kk] * rq;
            acc2 += st[(s0 + 16) * 65 + kk] * rq;
            acc3 += st[(s0 + 24) * 65 + kk] * rq;
        }
        __syncthreads();
    }
    float vv = gv[b * SS + t];
    const float sc = 1.0f / 32.0f;
    ssc[(s0 +  0) * 33 + t] = (acc0 + vv) * sc;
    ssc[(s0 +  8) * 33 + t] = (acc1 + vv) * sc;
    ssc[(s0 + 16) * 33 + t] = (acc2 + vv) * sc;
    ssc[(s0 + 24) * 33 + t] = (acc3 + vv) * sc;
    __syncthreads();
    if (tid < 32) {
        float mx = -1e30f;
        for (int j = 0; j < 32; j++) mx = fmaxf(mx, ssc[tid * 33 + j]);
        float sum = 0.0f;
        for (int j = 0; j < 32; j++) {
            float e = expf(ssc[tid * 33 + j] - mx);
            ssc[tid * 33 + j] = e; sum += e;
        }
        float inv = 1.0f / sum;
        for (int j = 0; j < 32; j++)
            attn[(size_t)b * SS * SS + tid * 32 + j] = ssc[tid * 33 + j] * inv;
    }
}

// ---------------------------------------------------------------------------
// classifier scalar + softmax halves -> d_a/d_v (out tail + scratch)
// ---------------------------------------------------------------------------
__global__ __launch_bounds__(512)
void cls_head_kernel(const float* __restrict__ h, const float* __restrict__ w2,
                     const float* __restrict__ b2, float* __restrict__ dav,
                     float* __restrict__ out_d)
{
    int b = blockIdx.x;
    __shared__ float sd[32];
    int w = threadIdx.x >> 5, lane = threadIdx.x & 31;
    for (int s = w; s < SS; s += 16) {
        const float* hr = h + ((size_t)b * SS + s) * HH;
        const float* wr = w2 + (size_t)s * HH;
        float acc = 0.0f;
        for (int k = lane; k < HH; k += 32) acc += hr[k] * wr[k];
#pragma unroll
        for (int o = 16; o; o >>= 1) acc += __shfl_down_sync(0xffffffffu, acc, o);
        if (lane == 0) sd[s] = fmaxf(acc + b2[s], 0.0f);
    }
    __syncthreads();
    if (threadIdx.x < 2) {
        int off = threadIdx.x * PP;
        float mx = -1e30f;
        for (int j = 0; j < PP; j++) mx = fmaxf(mx, sd[off + j]);
        float sum = 0.0f;
        float e[PP];
        for (int j = 0; j < PP; j++) { e[j] = expf(sd[off + j] - mx); sum += e[j]; }
        float inv = 1.0f / sum;
        float* outp = out_d + (size_t)threadIdx.x * BB * PP + (size_t)b * PP;
        for (int j = 0; j < PP; j++) {
            float val = e[j] * inv;
            dav[b * SS + off + j] = val;
            outp[j] = val;
        }
    }
}

// ---------------------------------------------------------------------------
// mix in q-space: wa[t]=sum_s d_a[s]attn[s,t]; avmix_a[b]=sum_t wa[t] q[b,t,:]
// ---------------------------------------------------------------------------
__global__ __launch_bounds__(128)
void combine_kernel(const float* __restrict__ attn, const float* __restrict__ q,
                    const float* __restrict__ dav, float* __restrict__ avmix)
{
    int b = blockIdx.x;
    __shared__ float sat[SS * SS];
    __shared__ float wa[SS], wvv[SS];
    int tid = threadIdx.x;
    for (int i = tid; i < SS * SS; i += 128) sat[i] = attn[(size_t)b * SS * SS + i];
    __syncthreads();
    if (tid < SS) {
        float a = 0.0f, v = 0.0f;
        for (int s = 0; s < PP; s++) {
            a += dav[b * SS + s]      * sat[s * SS + tid];
            v += dav[b * SS + PP + s] * sat[(PP + s) * SS + tid];
        }
        wa[tid] = a; wvv[tid] = v;
    }
    __syncthreads();
    const float* qb = q + (size_t)b * SS * DD;
    for (int d = tid; d < DD; d += 128) {
        float a = 0.0f, v = 0.0f;
#pragma unroll
        for (int t = 0; t < SS; t++) {
            float x = qb[(size_t)t * DD + d];
            a += wa[t] * x;
            v += wvv[t] * x;
        }
        avmix[(size_t)b * DD + d] = a;
        avmix[((size_t)BB + b) * DD + d] = v;
    }
}

// fusion = 0.5*(audio+video)
__global__ void avg_kernel(float* __restrict__ fav)
{
    size_t i = (size_t)blockIdx.x * 256 + threadIdx.x;
    fav[i] = 0.5f * (fav[(size_t)BB * DD + i] + fav[(size_t)2 * BB * DD + i]);
}

// ---------------------------------------------------------------------------
// LayerNorm(512) + ReLU per row
// ---------------------------------------------------------------------------
__global__ __launch_bounds__(128)
void ln_kernel(const float* __restrict__ x, const float* __restrict__ g,
               const float* __restrict__ be, float* __restrict__ out)
{
    int row = blockIdx.x;
    const float* xr = x + (size_t)row * FF;
    int tid = threadIdx.x;
    __shared__ float sm[4];
    float v[4];
    float s = 0.0f;
#pragma unroll
    for (int i = 0; i < 4; i++) { v[i] = xr[tid + 128 * i]; s += v[i]; }
#pragma unroll
    for (int o = 16; o; o >>= 1) s += __shfl_down_sync(0xffffffffu, s, o);
    if ((tid & 31) == 0) sm[tid >> 5] = s;
    __syncthreads();
    float mu = (sm[0] + sm[1] + sm[2] + sm[3]) * (1.0f / FF);
    __syncthreads();
    float qv = 0.0f;
#pragma unroll
    for (int i = 0; i < 4; i++) { float d = v[i] - mu; qv += d * d; }
#pragma unroll
    for (int o = 16; o; o >>= 1) qv += __shfl_down_sync(0xffffffffu, qv, o);
    if ((tid & 31) == 0) sm[tid >> 5] = qv;
    __syncthreads();
    float var = (sm[0] + sm[1] + sm[2] + sm[3]) * (1.0f / FF);
    float rstd = rsqrtf(var + 1e-5f);
    float* orow = out + (size_t)row * FF;
#pragma unroll
    for (int i = 0; i < 4; i++) {
        int c = tid + 128 * i;
        float y = (v[i] - mu) * rstd * g[c] + be[c];
        orow[c] = fmaxf(y, 0.0f);
    }
}

// ---------------------------------------------------------------------------
extern "C" void kernel_launch(void* const* d_in, const int* in_sizes, int n_in,
                              void* d_out, int out_size)
{
    const float* q      = (const float*)d_in[0];
    const float* in_w   = (const float*)d_in[1];
    const float* in_b   = (const float*)d_in[2];
    const float* out_w  = (const float*)d_in[3];
    const float* out_b  = (const float*)d_in[4];
    const float* cls_w1 = (const float*)d_in[5];
    const float* cls_b1 = (const float*)d_in[6];
    const float* cls_w2 = (const float*)d_in[7];
    const float* cls_b2 = (const float*)d_in[8];
    const float* fus_w  = (const float*)d_in[9];
    const float* fus_b  = (const float*)d_in[10];
    const float* fus_g  = (const float*)d_in[11];
    const float* fus_be = (const float*)d_in[12];
    const float* pa_w   = (const float*)d_in[13];
    const float* pa_b   = (const float*)d_in[14];
    const float* pa_g   = (const float*)d_in[15];
    const float* pa_be  = (const float*)d_in[16];
    const float* pv_w   = (const float*)d_in[17];
    const float* pv_b   = (const float*)d_in[18];
    const float* pv_g   = (const float*)d_in[19];
    const float* pv_be  = (const float*)d_in[20];
    float* out = (float*)d_out;

    float* sp = nullptr;
    cudaGetSymbolAddress((void**)&sp, g_scratch);

    float* t1    = sp + OF_T1;
    float* h     = sp + OF_H;
    float* attn  = sp + OF_ATTN;
    float* gv    = sp + OF_GV;
    float* dav   = sp + OF_DAV;
    float* avmix = sp + OF_AVMIX;
    float* avpre = sp + OF_AVPRE;
    float* fav   = sp + OF_FAV;
    float* headb = sp + OF_HEAD;
    float* Mt    = sp + OF_MT;
    float* WqT   = sp + OF_WT;
    float* WkT   = sp + OF_WT + (size_t)DD * DD;
    float* wv    = sp + OF_WV;

    const float* wv_w = in_w + (size_t)2 * DD * DD;
    const float* bv = in_b + 2 * DD;

    // 1. WqT, WkT transposes
    tr1024<<<dim3(32, 32, 2), dim3(32, 8)>>>(in_w, WqT);
    // 2. bias fold
    vec_kernel<<<4, 256>>>(in_w, in_b, wv);
    // 3. Mt[n,k] = sum_e WkT[n,e]*WqT[k,e]   (bf16 3-pass, full precision)
    mma_gemm<<<dim3(8, 8, 1), 256>>>(WkT, DD, 0, WqT, DD, 0, nullptr, 0,
                                     Mt, DD, 0, DD, 0);
    // 4. t1 = q @ M   (tf32 single-pass)
    tf32_gemm<<<dim3(8, 512, 1), 256>>>(q, DD, 0, Mt, DD, 0, nullptr, 0,
                                        t1, DD, 0, DD, 0);
    // 5. h = relu(q @ W1[s]^T + b1[s])   (tf32 single-pass)
    tf32_gemm<<<dim3(4, 16, 32), 256>>>(q, SS * DD, DD,
                                        cls_w1, DD, (long long)HH * DD,
                                        cls_b1, HH, h, SS * HH, HH, DD, 1);
    // 6. gv
    uv_kernel<<<BB, 1024>>>(q, wv, gv);
    // 7. attention softmax
    attn_kernel<<<BB, 256>>>(q, t1, gv, attn);
    // 8. classifier head -> dav + out tail
    cls_head_kernel<<<BB, 512>>>(h, cls_w2, cls_b2, dav, out + (size_t)3 * BB * FF);
    // 9. q-space mix
    combine_kernel<<<BB, 128>>>(attn, q, dav, avmix);
    // 10. avpre = avmix @ Wv^T + bv
    mma_gemm<<<dim3(8, 32, 1), 256>>>(avmix, DD, 0, wv_w, DD, 0, bv, 0,
                                      avpre, DD, 0, DD, 0);
    // 11. audio/video = avpre @ out_w^T + out_b -> fav[B..3B)
    mma_gemm<<<dim3(8, 32, 1), 256>>>(avpre, DD, 0, out_w, DD, 0, out_b, 0,
                                      fav + (size_t)BB * DD, DD, 0, DD, 0);
    // 12. fusion
    avg_kernel<<<(BB * DD) / 256, 256>>>(fav);
    // 13-15. projector heads
    mma_gemm<<<dim3(4, 16, 1), 256>>>(fav, DD, 0, fus_w, DD, 0, fus_b, 0,
                                      headb, FF, 0, DD, 0);
    mma_gemm<<<dim3(4, 16, 1), 256>>>(fav + (size_t)BB * DD, DD, 0, pa_w, DD, 0,
                                      pa_b, 0, headb + (size_t)BB * FF, FF, 0, DD, 0);
    mma_gemm<<<dim3(4, 16, 1), 256>>>(fav + (size_t)2 * BB * DD, DD, 0, pv_w, DD, 0,
                                      pv_b, 0, headb + (size_t)2 * BB * FF, FF, 0, DD, 0);
    // 16-18. LayerNorm + ReLU
    ln_kernel<<<BB, 128>>>(headb, fus_g, fus_be, out);
    ln_kernel<<<BB, 128>>>(headb + (size_t)BB * FF, pa_g, pa_be, out + (size_t)BB * FF);
    ln_kernel<<<BB, 128>>>(headb + (size_t)2 * BB * FF, pv_g, pv_be, out + (size_t)2 * BB * FF);
}